// round 13
// baseline (speedup 1.0000x reference)
#include <cuda_runtime.h>

// Scratch via __device__ globals (no allocations allowed).
#define NBLOCKS 592    // 148 SMs x 4 resident CTAs -> exactly one wave
__device__ double g_partials[NBLOCKS];
__device__ unsigned int g_retire_count = 0;  // reset to 0 by last block each run

// 256-bit streaming load (sm_100+): one LDG.E.256 per 8 floats.
__device__ __forceinline__ void ldg256(const float* p, float* v) {
    asm volatile(
        "ld.global.nc.v8.f32 {%0, %1, %2, %3, %4, %5, %6, %7}, [%8];"
        : "=f"(v[0]), "=f"(v[1]), "=f"(v[2]), "=f"(v[3]),
          "=f"(v[4]), "=f"(v[5]), "=f"(v[6]), "=f"(v[7])
        : "l"(p));
}

// Single fused kernel, single wave: grid-stride over 32-byte packets with two
// independent 256-bit loads per iteration, pointer-bump addressing (no
// per-iteration IMAD.WIDE on the load addresses). Per-block partial into a
// dedicated slot; last retiring block reduces partials and writes the mean.
// Graph-replayable (retire counter self-resets).
__global__ void __launch_bounds__(512, 4)
bins_combiner_kernel(const float* __restrict__ p,
                     const float* __restrict__ c,
                     int n8,                      // count of 8-float packets
                     const float* __restrict__ p_tail,
                     const float* __restrict__ c_tail,
                     int n_tail,
                     float* __restrict__ out,
                     double inv_rows) {
    float acc0 = 0.0f, acc1 = 0.0f;

    int idx    = blockIdx.x * blockDim.x + threadIdx.x;
    int stride = gridDim.x * blockDim.x;   // 592*512 = 303104

    // Iterations this thread executes: ceil((n8 - idx) / stride), 0 if idx>=n8.
    int iters = (idx < n8) ? ((n8 - 1 - idx) / stride + 1) : 0;

    const float* pp = p + (long long)idx * 8;
    const float* cc = c + (long long)idx * 8;
    const long long step = (long long)stride * 8;   // floats per hop

    for (int it = 0; it < iters; ++it) {
        float a[8], b[8];
        ldg256(pp, a);
        ldg256(cc, b);
        pp += step;
        cc += step;
        acc0 = fmaf(a[0], b[0], acc0);
        acc1 = fmaf(a[1], b[1], acc1);
        acc0 = fmaf(a[2], b[2], acc0);
        acc1 = fmaf(a[3], b[3], acc1);
        acc0 = fmaf(a[4], b[4], acc0);
        acc1 = fmaf(a[5], b[5], acc1);
        acc0 = fmaf(a[6], b[6], acc0);
        acc1 = fmaf(a[7], b[7], acc1);
    }

    float acc = acc0 + acc1;

    // Scalar tail (n divisible by 8 here -> n_tail==0; kept for generality).
    if (idx < n_tail) {
        acc = fmaf(p_tail[idx], c_tail[idx], acc);
    }

    // Warp reduction.
    #pragma unroll
    for (int off = 16; off > 0; off >>= 1)
        acc += __shfl_xor_sync(0xFFFFFFFFu, acc, off);

    // Block reduction via shared memory.
    __shared__ float warp_sums[16];  // 512 threads -> 16 warps
    __shared__ bool  is_last;
    int lane = threadIdx.x & 31;
    int wid  = threadIdx.x >> 5;
    if (lane == 0) warp_sums[wid] = acc;
    __syncthreads();

    if (wid == 0) {
        float v = (lane < 16) ? warp_sums[lane] : 0.0f;
        #pragma unroll
        for (int off = 16; off > 0; off >>= 1)
            v += __shfl_xor_sync(0xFFFFFFFFu, v, off);
        if (lane == 0) {
            g_partials[blockIdx.x] = (double)v;
            __threadfence();
            unsigned int prev = atomicAdd(&g_retire_count, 1u);
            is_last = (prev == gridDim.x - 1);
        }
    }
    __syncthreads();

    if (is_last) {
        __threadfence();  // acquire: make all partials visible
        // 592 doubles reduced across 512 threads (threads 0..79 take 2).
        double d = 0.0;
        for (unsigned int j = threadIdx.x; j < gridDim.x; j += blockDim.x)
            d += g_partials[j];
        #pragma unroll
        for (int off = 16; off > 0; off >>= 1)
            d += __shfl_xor_sync(0xFFFFFFFFu, d, off);

        __shared__ double dwarp[16];
        if (lane == 0) dwarp[wid] = d;
        __syncthreads();
        if (wid == 0) {
            double t = (lane < 16) ? dwarp[lane] : 0.0;
            #pragma unroll
            for (int off = 16; off > 0; off >>= 1)
                t += __shfl_xor_sync(0xFFFFFFFFu, t, off);
            if (lane == 0) {
                out[0] = (float)(t * inv_rows);
                __threadfence();
                g_retire_count = 0;  // reset for next graph replay
            }
        }
    }
}

extern "C" void kernel_launch(void* const* d_in, const int* in_sizes, int n_in,
                              void* d_out, int out_size) {
    const float* probs     = (const float*)d_in[0];
    const float* centroids = (const float*)d_in[1];
    float* out = (float*)d_out;

    long long n = (long long)in_sizes[0];   // N*K total elements (~1.01e8)
    const int K = 101;
    long long rows = n / K;

    int n8 = (int)(n >> 3);                 // 8-float packet count (12,625,000)
    long long tail_start = (long long)n8 << 3;
    int n_tail = (int)(n - tail_start);     // 0 for this shape

    bins_combiner_kernel<<<NBLOCKS, 512>>>(
        probs, centroids, n8,
        probs + tail_start, centroids + tail_start, n_tail,
        out, 1.0 / (double)rows);
}

// round 14
// speedup vs baseline: 1.2572x; 1.2572x over previous
#include <cuda_runtime.h>

// Scratch via __device__ globals (no allocations allowed).
#define NBLOCKS 592    // 148 SMs x 4 resident CTAs -> exactly one wave
__device__ double g_partials[NBLOCKS];
__device__ unsigned int g_retire_count = 0;  // reset to 0 by last block each run

// 256-bit streaming load (sm_100+): one LDG.E.256 per 8 floats.
__device__ __forceinline__ void ldg256(const float* p, float* v) {
    asm volatile(
        "ld.global.nc.v8.f32 {%0, %1, %2, %3, %4, %5, %6, %7}, [%8];"
        : "=f"(v[0]), "=f"(v[1]), "=f"(v[2]), "=f"(v[3]),
          "=f"(v[4]), "=f"(v[5]), "=f"(v[6]), "=f"(v[7])
        : "l"(p));
}

// Single fused kernel, single wave: grid-stride over 32-byte packets with
// two independent 256-bit loads per iteration. Per-block partial into a
// dedicated slot; last retiring block reduces partials and writes the mean.
// Graph-replayable (retire counter self-resets).
__global__ void __launch_bounds__(512, 4)
bins_combiner_kernel(const float* __restrict__ p,
                     const float* __restrict__ c,
                     int n8,                      // count of 8-float packets
                     const float* __restrict__ p_tail,
                     const float* __restrict__ c_tail,
                     int n_tail,
                     float* __restrict__ out,
                     double inv_rows) {
    float acc0 = 0.0f, acc1 = 0.0f;

    int idx    = blockIdx.x * blockDim.x + threadIdx.x;
    int stride = gridDim.x * blockDim.x;   // 592*512 = 303104

    for (int i = idx; i < n8; i += stride) {
        float a[8], b[8];
        ldg256(p + (long long)i * 8, a);
        ldg256(c + (long long)i * 8, b);
        acc0 = fmaf(a[0], b[0], acc0);
        acc1 = fmaf(a[1], b[1], acc1);
        acc0 = fmaf(a[2], b[2], acc0);
        acc1 = fmaf(a[3], b[3], acc1);
        acc0 = fmaf(a[4], b[4], acc0);
        acc1 = fmaf(a[5], b[5], acc1);
        acc0 = fmaf(a[6], b[6], acc0);
        acc1 = fmaf(a[7], b[7], acc1);
    }

    float acc = acc0 + acc1;

    // Scalar tail (n divisible by 8 here -> n_tail==0; kept for generality).
    if (idx < n_tail) {
        acc = fmaf(p_tail[idx], c_tail[idx], acc);
    }

    // Warp reduction.
    #pragma unroll
    for (int off = 16; off > 0; off >>= 1)
        acc += __shfl_xor_sync(0xFFFFFFFFu, acc, off);

    // Block reduction via shared memory.
    __shared__ float warp_sums[16];  // 512 threads -> 16 warps
    __shared__ bool  is_last;
    int lane = threadIdx.x & 31;
    int wid  = threadIdx.x >> 5;
    if (lane == 0) warp_sums[wid] = acc;
    __syncthreads();

    if (wid == 0) {
        float v = (lane < 16) ? warp_sums[lane] : 0.0f;
        #pragma unroll
        for (int off = 16; off > 0; off >>= 1)
            v += __shfl_xor_sync(0xFFFFFFFFu, v, off);
        if (lane == 0) {
            g_partials[blockIdx.x] = (double)v;
            __threadfence();
            unsigned int prev = atomicAdd(&g_retire_count, 1u);
            is_last = (prev == gridDim.x - 1);
        }
    }
    __syncthreads();

    if (is_last) {
        __threadfence();  // acquire: make all partials visible
        // 592 doubles reduced across 512 threads (threads 0..79 take 2).
        double d = 0.0;
        for (unsigned int j = threadIdx.x; j < gridDim.x; j += blockDim.x)
            d += g_partials[j];
        #pragma unroll
        for (int off = 16; off > 0; off >>= 1)
            d += __shfl_xor_sync(0xFFFFFFFFu, d, off);

        __shared__ double dwarp[16];
        if (lane == 0) dwarp[wid] = d;
        __syncthreads();
        if (wid == 0) {
            double t = (lane < 16) ? dwarp[lane] : 0.0;
            #pragma unroll
            for (int off = 16; off > 0; off >>= 1)
                t += __shfl_xor_sync(0xFFFFFFFFu, t, off);
            if (lane == 0) {
                out[0] = (float)(t * inv_rows);
                __threadfence();
                g_retire_count = 0;  // reset for next graph replay
            }
        }
    }
}

extern "C" void kernel_launch(void* const* d_in, const int* in_sizes, int n_in,
                              void* d_out, int out_size) {
    const float* probs     = (const float*)d_in[0];
    const float* centroids = (const float*)d_in[1];
    float* out = (float*)d_out;

    long long n = (long long)in_sizes[0];   // N*K total elements (~1.01e8)
    const int K = 101;
    long long rows = n / K;

    int n8 = (int)(n >> 3);                 // 8-float packet count (12,625,000)
    long long tail_start = (long long)n8 << 3;
    int n_tail = (int)(n - tail_start);     // 0 for this shape

    bins_combiner_kernel<<<NBLOCKS, 512>>>(
        probs, centroids, n8,
        probs + tail_start, centroids + tail_start, n_tail,
        out, 1.0 / (double)rows);
}

// round 15
// speedup vs baseline: 1.2599x; 1.0021x over previous
#include <cuda_runtime.h>

// Scratch via __device__ globals (no allocations allowed).
#define NBLOCKS 592    // 148 SMs x 4 resident CTAs -> exactly one wave
__device__ double g_partials[NBLOCKS];
__device__ unsigned int g_retire_count = 0;  // reset to 0 by last block each run

// 256-bit streaming load (sm_100+): one LDG.E.256 per 8 floats.
__device__ __forceinline__ void ldg256(const float* p, float* v) {
    asm volatile(
        "ld.global.nc.v8.f32 {%0, %1, %2, %3, %4, %5, %6, %7}, [%8];"
        : "=f"(v[0]), "=f"(v[1]), "=f"(v[2]), "=f"(v[3]),
          "=f"(v[4]), "=f"(v[5]), "=f"(v[6]), "=f"(v[7])
        : "l"(p));
}

// Single fused kernel, single wave: grid-stride over 32-byte packets with
// two independent 256-bit loads per iteration. Per-block partial into a
// dedicated slot; last retiring block reduces partials and writes the mean.
// Graph-replayable (retire counter self-resets).
__global__ void __launch_bounds__(512, 4)
bins_combiner_kernel(const float* __restrict__ p,
                     const float* __restrict__ c,
                     int n8,                      // count of 8-float packets
                     const float* __restrict__ p_tail,
                     const float* __restrict__ c_tail,
                     int n_tail,
                     float* __restrict__ out,
                     double inv_rows) {
    float acc0 = 0.0f, acc1 = 0.0f;

    int idx    = blockIdx.x * blockDim.x + threadIdx.x;
    int stride = gridDim.x * blockDim.x;   // 592*512 = 303104

    for (int i = idx; i < n8; i += stride) {
        float a[8], b[8];
        ldg256(p + (long long)i * 8, a);
        ldg256(c + (long long)i * 8, b);
        acc0 = fmaf(a[0], b[0], acc0);
        acc1 = fmaf(a[1], b[1], acc1);
        acc0 = fmaf(a[2], b[2], acc0);
        acc1 = fmaf(a[3], b[3], acc1);
        acc0 = fmaf(a[4], b[4], acc0);
        acc1 = fmaf(a[5], b[5], acc1);
        acc0 = fmaf(a[6], b[6], acc0);
        acc1 = fmaf(a[7], b[7], acc1);
    }

    float acc = acc0 + acc1;

    // Scalar tail (n divisible by 8 here -> n_tail==0; kept for generality).
    if (idx < n_tail) {
        acc = fmaf(p_tail[idx], c_tail[idx], acc);
    }

    // Warp reduction.
    #pragma unroll
    for (int off = 16; off > 0; off >>= 1)
        acc += __shfl_xor_sync(0xFFFFFFFFu, acc, off);

    // Block reduction via shared memory.
    __shared__ float warp_sums[16];  // 512 threads -> 16 warps
    __shared__ bool  is_last;
    int lane = threadIdx.x & 31;
    int wid  = threadIdx.x >> 5;
    if (lane == 0) warp_sums[wid] = acc;
    __syncthreads();

    if (wid == 0) {
        float v = (lane < 16) ? warp_sums[lane] : 0.0f;
        #pragma unroll
        for (int off = 16; off > 0; off >>= 1)
            v += __shfl_xor_sync(0xFFFFFFFFu, v, off);
        if (lane == 0) {
            g_partials[blockIdx.x] = (double)v;
            __threadfence();
            unsigned int prev = atomicAdd(&g_retire_count, 1u);
            is_last = (prev == gridDim.x - 1);
        }
    }
    __syncthreads();

    if (is_last) {
        __threadfence();  // acquire: make all partials visible
        // 592 doubles reduced across 512 threads (threads 0..79 take 2).
        double d = 0.0;
        for (unsigned int j = threadIdx.x; j < gridDim.x; j += blockDim.x)
            d += g_partials[j];
        #pragma unroll
        for (int off = 16; off > 0; off >>= 1)
            d += __shfl_xor_sync(0xFFFFFFFFu, d, off);

        __shared__ double dwarp[16];
        if (lane == 0) dwarp[wid] = d;
        __syncthreads();
        if (wid == 0) {
            double t = (lane < 16) ? dwarp[lane] : 0.0;
            #pragma unroll
            for (int off = 16; off > 0; off >>= 1)
                t += __shfl_xor_sync(0xFFFFFFFFu, t, off);
            if (lane == 0) {
                out[0] = (float)(t * inv_rows);
                __threadfence();
                g_retire_count = 0;  // reset for next graph replay
            }
        }
    }
}

extern "C" void kernel_launch(void* const* d_in, const int* in_sizes, int n_in,
                              void* d_out, int out_size) {
    const float* probs     = (const float*)d_in[0];
    const float* centroids = (const float*)d_in[1];
    float* out = (float*)d_out;

    long long n = (long long)in_sizes[0];   // N*K total elements (~1.01e8)
    const int K = 101;
    long long rows = n / K;

    int n8 = (int)(n >> 3);                 // 8-float packet count (12,625,000)
    long long tail_start = (long long)n8 << 3;
    int n_tail = (int)(n - tail_start);     // 0 for this shape

    bins_combiner_kernel<<<NBLOCKS, 512>>>(
        probs, centroids, n8,
        probs + tail_start, centroids + tail_start, n_tail,
        out, 1.0 / (double)rows);
}

// round 16
// speedup vs baseline: 1.2606x; 1.0005x over previous
#include <cuda_runtime.h>

// Scratch via __device__ globals (no allocations allowed).
#define NBLOCKS 1184   // 148 SMs x 8 resident 256-thread CTAs -> exactly one wave
__device__ double g_partials[NBLOCKS];
__device__ unsigned int g_retire_count = 0;  // reset to 0 by last block each run

// 256-bit streaming load (sm_100+): one LDG.E.256 per 8 floats.
__device__ __forceinline__ void ldg256(const float* p, float* v) {
    asm volatile(
        "ld.global.nc.v8.f32 {%0, %1, %2, %3, %4, %5, %6, %7}, [%8];"
        : "=f"(v[0]), "=f"(v[1]), "=f"(v[2]), "=f"(v[3]),
          "=f"(v[4]), "=f"(v[5]), "=f"(v[6]), "=f"(v[7])
        : "l"(p));
}

// Single fused kernel, single wave: grid-stride over 32-byte packets with
// two independent 256-bit loads per iteration. Per-block partial into a
// dedicated slot; last retiring block reduces partials and writes the mean.
// Graph-replayable (retire counter self-resets).
__global__ void __launch_bounds__(256, 8)
bins_combiner_kernel(const float* __restrict__ p,
                     const float* __restrict__ c,
                     int n8,                      // count of 8-float packets
                     const float* __restrict__ p_tail,
                     const float* __restrict__ c_tail,
                     int n_tail,
                     float* __restrict__ out,
                     double inv_rows) {
    float acc0 = 0.0f, acc1 = 0.0f;

    int idx    = blockIdx.x * blockDim.x + threadIdx.x;
    int stride = gridDim.x * blockDim.x;   // 1184*256 = 303104 (same as before)

    for (int i = idx; i < n8; i += stride) {
        float a[8], b[8];
        ldg256(p + (long long)i * 8, a);
        ldg256(c + (long long)i * 8, b);
        acc0 = fmaf(a[0], b[0], acc0);
        acc1 = fmaf(a[1], b[1], acc1);
        acc0 = fmaf(a[2], b[2], acc0);
        acc1 = fmaf(a[3], b[3], acc1);
        acc0 = fmaf(a[4], b[4], acc0);
        acc1 = fmaf(a[5], b[5], acc1);
        acc0 = fmaf(a[6], b[6], acc0);
        acc1 = fmaf(a[7], b[7], acc1);
    }

    float acc = acc0 + acc1;

    // Scalar tail (n divisible by 8 here -> n_tail==0; kept for generality).
    if (idx < n_tail) {
        acc = fmaf(p_tail[idx], c_tail[idx], acc);
    }

    // Warp reduction.
    #pragma unroll
    for (int off = 16; off > 0; off >>= 1)
        acc += __shfl_xor_sync(0xFFFFFFFFu, acc, off);

    // Block reduction via shared memory.
    __shared__ float warp_sums[8];   // 256 threads -> 8 warps
    __shared__ bool  is_last;
    int lane = threadIdx.x & 31;
    int wid  = threadIdx.x >> 5;
    if (lane == 0) warp_sums[wid] = acc;
    __syncthreads();

    if (wid == 0) {
        float v = (lane < 8) ? warp_sums[lane] : 0.0f;
        #pragma unroll
        for (int off = 4; off > 0; off >>= 1)
            v += __shfl_xor_sync(0xFFFFFFFFu, v, off);
        if (lane == 0) {
            g_partials[blockIdx.x] = (double)v;
            __threadfence();
            unsigned int prev = atomicAdd(&g_retire_count, 1u);
            is_last = (prev == gridDim.x - 1);
        }
    }
    __syncthreads();

    if (is_last) {
        __threadfence();  // acquire: make all partials visible
        // 1184 doubles reduced across 256 threads (each takes 4-5).
        double d = 0.0;
        for (unsigned int j = threadIdx.x; j < gridDim.x; j += blockDim.x)
            d += g_partials[j];
        #pragma unroll
        for (int off = 16; off > 0; off >>= 1)
            d += __shfl_xor_sync(0xFFFFFFFFu, d, off);

        __shared__ double dwarp[8];
        if (lane == 0) dwarp[wid] = d;
        __syncthreads();
        if (wid == 0) {
            double t = (lane < 8) ? dwarp[lane] : 0.0;
            #pragma unroll
            for (int off = 4; off > 0; off >>= 1)
                t += __shfl_xor_sync(0xFFFFFFFFu, t, off);
            if (lane == 0) {
                out[0] = (float)(t * inv_rows);
                __threadfence();
                g_retire_count = 0;  // reset for next graph replay
            }
        }
    }
}

extern "C" void kernel_launch(void* const* d_in, const int* in_sizes, int n_in,
                              void* d_out, int out_size) {
    const float* probs     = (const float*)d_in[0];
    const float* centroids = (const float*)d_in[1];
    float* out = (float*)d_out;

    long long n = (long long)in_sizes[0];   // N*K total elements (~1.01e8)
    const int K = 101;
    long long rows = n / K;

    int n8 = (int)(n >> 3);                 // 8-float packet count (12,625,000)
    long long tail_start = (long long)n8 << 3;
    int n_tail = (int)(n - tail_start);     // 0 for this shape

    bins_combiner_kernel<<<NBLOCKS, 256>>>(
        probs, centroids, n8,
        probs + tail_start, centroids + tail_start, n_tail,
        out, 1.0 / (double)rows);
}